// round 1
// baseline (speedup 1.0000x reference)
#include <cuda_runtime.h>

// ---------------- scratch (device globals; no allocation allowed) ----------
__device__ float g_r1b [1179648];  // [2][64][96][96]  after refine conv1
__device__ float g_r2b [1179648];  // [2][64][96][96]  query features q
__device__ float g_t48 [294912];   // [2][64][48][48]  bn(conv1x1(c2))
__device__ float g_c2r [1179648];  // [2][64][96][96]  relu(upsample(t48)) = keys
__device__ float g_attb[165888];   // [2][9][9216]     softmax attention
__device__ float g_pool[204800];   // [2][2048*50]     pooled x (scales 1,2,3,6 packed)
__device__ float g_ppol[51200];    // [2][512*50]      relu(bn(1x1 conv)) of pooled
__device__ float g_psp [18874368]; // [2][4096][48][48] concat psp features
__device__ float g_out5[2359296];  // [2][512][48][48] conv5 output
__device__ float g_z48 [271872];   // [2][59][48][48]  conv6(out) (no bias)
__device__ float g_z96 [1087488];  // [2][59][96][96]  upsampled z

// ---------------------------------------------------------------------------
// Generic tiled SGEMM with on-the-fly im2col B-loader + fused BN/ReLU.
//   C[m,p] = sum_k A[m,k] * B[k,p]
//   DIL==0 : B[k,p] = Bin[k*Npix + p]                 (1x1 conv)
//   DIL>0  : k=cin*9+tap, 3x3 conv w/ dilation DIL, pad DIL, zero-padded
// Tile: TM x 128 x 8, thread micro-tile 8x8, double buffered smem.
// ---------------------------------------------------------------------------
template<int TM, int DIL, bool BN, bool RELU, bool MCHECK, bool NCHECK>
__global__ void __launch_bounds__((TM/8)*16, 1)
gemm_conv(const float* __restrict__ A, const float* __restrict__ Bin,
          const float* __restrict__ bnp, float* __restrict__ Out,
          int M, int K, int H, int W, int Npix,
          long inStride, long outStride)
{
    constexpr int TN   = 128;
    constexpr int NT   = (TM / 8) * (TN / 8);
    constexpr int BVEC = (NT == 256) ? 4 : 8;

    __shared__ float As[2][8][TM];
    __shared__ float Bs[2][8][TN];

    const int tid = threadIdx.x;
    const int img = blockIdx.z;
    const float* Bn = Bin + (long)img * inStride;
    float*       On = Out + (long)img * outStride;
    const int bm  = blockIdx.y * TM;
    const int bp0 = blockIdx.x * TN;
    const int tr  = tid / 16;
    const int tc  = tid % 16;

    const int am = tid >> 1;
    const int ak = (tid & 1) * 4;
    const int bk = tid / (TN / BVEC);
    const int bp = (tid % (TN / BVEC)) * BVEC;

    float4 aReg;
    float  bReg[BVEC];

    auto fetch = [&](int k0) {
        int m = bm + am;
        if (!MCHECK || m < M)
            aReg = *reinterpret_cast<const float4*>(A + (long)m * K + k0 + ak);
        else
            aReg = make_float4(0.f, 0.f, 0.f, 0.f);
        int k = k0 + bk;
        if (DIL == 0) {
            const float* row = Bn + (long)k * Npix;
            if (!NCHECK) {
                #pragma unroll
                for (int j = 0; j < BVEC; j += 4) {
                    float4 v = *reinterpret_cast<const float4*>(row + bp0 + bp + j);
                    bReg[j] = v.x; bReg[j+1] = v.y; bReg[j+2] = v.z; bReg[j+3] = v.w;
                }
            } else {
                #pragma unroll
                for (int j = 0; j < BVEC; j++) {
                    int p = bp0 + bp + j;
                    bReg[j] = (p < Npix) ? row[p] : 0.f;
                }
            }
        } else {
            int cin = k / 9;
            int tap = k - cin * 9;
            int oy  = (tap / 3 - 1) * DIL;
            int ox  = (tap % 3 - 1) * DIL;
            const float* src = Bn + (long)cin * (H * W);
            #pragma unroll
            for (int j = 0; j < BVEC; j++) {
                int p  = bp0 + bp + j;
                int py = p / W;
                int px = p - py * W;
                int y  = py + oy;
                int x  = px + ox;
                bReg[j] = ((unsigned)y < (unsigned)H && (unsigned)x < (unsigned)W)
                          ? src[y * W + x] : 0.f;
            }
        }
    };
    auto put = [&](int buf) {
        As[buf][ak + 0][am] = aReg.x;
        As[buf][ak + 1][am] = aReg.y;
        As[buf][ak + 2][am] = aReg.z;
        As[buf][ak + 3][am] = aReg.w;
        #pragma unroll
        for (int j = 0; j < BVEC; j++) Bs[buf][bk][bp + j] = bReg[j];
    };

    float acc[8][8];
    #pragma unroll
    for (int i = 0; i < 8; i++)
        #pragma unroll
        for (int j = 0; j < 8; j++) acc[i][j] = 0.f;

    fetch(0);
    put(0);
    __syncthreads();

    const int nK = K / 8;
    int buf = 0;
    for (int it = 0; it < nK; it++) {
        if (it + 1 < nK) fetch((it + 1) * 8);
        #pragma unroll
        for (int kk = 0; kk < 8; kk++) {
            float4 a0 = *reinterpret_cast<const float4*>(&As[buf][kk][tr * 8]);
            float4 a1 = *reinterpret_cast<const float4*>(&As[buf][kk][tr * 8 + 4]);
            float4 b0 = *reinterpret_cast<const float4*>(&Bs[buf][kk][tc * 8]);
            float4 b1 = *reinterpret_cast<const float4*>(&Bs[buf][kk][tc * 8 + 4]);
            float av[8] = {a0.x, a0.y, a0.z, a0.w, a1.x, a1.y, a1.z, a1.w};
            float bv[8] = {b0.x, b0.y, b0.z, b0.w, b1.x, b1.y, b1.z, b1.w};
            #pragma unroll
            for (int i = 0; i < 8; i++)
                #pragma unroll
                for (int j = 0; j < 8; j++)
                    acc[i][j] = fmaf(av[i], bv[j], acc[i][j]);
        }
        if (it + 1 < nK) put(buf ^ 1);
        __syncthreads();
        buf ^= 1;
    }

    #pragma unroll
    for (int i = 0; i < 8; i++) {
        int m = bm + tr * 8 + i;
        if (MCHECK && m >= M) continue;
        float scale = 1.f, shift = 0.f;
        if (BN) {
            float g  = bnp[m];
            float be = bnp[M + m];
            float mu = bnp[2 * M + m];
            float va = bnp[3 * M + m];
            scale = g * rsqrtf(va + 1e-5f);
            shift = be - mu * scale;
        }
        #pragma unroll
        for (int j = 0; j < 8; j++) {
            int p = bp0 + tc * 8 + j;
            if (NCHECK && p >= Npix) continue;
            float v = acc[i][j];
            if (BN)   v = fmaf(v, scale, shift);
            if (RELU) v = fmaxf(v, 0.f);
            On[(long)m * Npix + p] = v;
        }
    }
}

// -------- adaptive avg pool of x at scales 1,2,3,6 (packed layout) ---------
__global__ void pool_kernel(const float* __restrict__ x, float* __restrict__ pool)
{
    __shared__ float sm[2304];
    const int cin = blockIdx.x;     // 0..2047
    const int n   = blockIdx.y;     // 0..1
    const float* src = x + ((long)n * 2048 + cin) * 2304;
    for (int i = threadIdx.x; i < 2304; i += blockDim.x) sm[i] = src[i];
    __syncthreads();
    int r = threadIdx.x;
    if (r < 50) {
        int sc, pi;
        if      (r < 1)  { sc = 0; pi = r; }
        else if (r < 5)  { sc = 1; pi = r - 1; }
        else if (r < 14) { sc = 2; pi = r - 5; }
        else             { sc = 3; pi = r - 14; }
        const int sides[4] = {1, 2, 3, 6};
        const int inoff[4] = {0, 2048, 10240, 28672};
        int side = sides[sc];
        int iy = pi / side, ix = pi % side;
        int bs = 48 / side;
        float s = 0.f;
        for (int yy = iy * bs; yy < (iy + 1) * bs; yy++)
            for (int xx = ix * bs; xx < (ix + 1) * bs; xx++)
                s += sm[yy * 48 + xx];
        pool[(long)n * 102400 + inoff[sc] + cin * (side * side) + pi] = s / (float)(bs * bs);
    }
}

// -------- 1x1 conv (2048->512) + BN + ReLU on the tiny pooled grids --------
struct PoolWArgs { const float* w[4]; const float* bn[4]; };

__global__ void pooled_conv_kernel(PoolWArgs args, const float* __restrict__ pool,
                                   float* __restrict__ ppool)
{
    int gw   = (blockIdx.x * blockDim.x + threadIdx.x) >> 5;
    int lane = threadIdx.x & 31;
    if (gw >= 51200) return;
    int n  = gw / 25600;
    int t  = gw % 25600;
    int pg = t / 512;
    int co = t % 512;
    int sc, pi;
    if      (pg < 1)  { sc = 0; pi = pg; }
    else if (pg < 5)  { sc = 1; pi = pg - 1; }
    else if (pg < 14) { sc = 2; pi = pg - 5; }
    else              { sc = 3; pi = pg - 14; }
    const int ssq[4]    = {1, 4, 9, 36};
    const int inoff[4]  = {0, 2048, 10240, 28672};
    const int outoff[4] = {0, 512, 2560, 7168};
    const float* w  = args.w[sc] + (long)co * 2048;
    const float* pb = pool + (long)n * 102400 + inoff[sc] + pi;
    int stride = ssq[sc];
    float acc = 0.f;
    for (int c = lane; c < 2048; c += 32)
        acc = fmaf(w[c], pb[(long)c * stride], acc);
    #pragma unroll
    for (int s = 16; s; s >>= 1) acc += __shfl_xor_sync(0xffffffffu, acc, s);
    if (lane == 0) {
        const float* bnp = args.bn[sc];
        float scale = bnp[co] * rsqrtf(bnp[1536 + co] + 1e-5f);
        float v = fmaf(acc, scale, bnp[512 + co] - bnp[1024 + co] * scale);
        ppool[(long)n * 25600 + outoff[sc] + co * stride + pi] = fmaxf(v, 0.f);
    }
}

// -------- assemble psp = concat(x, up(s1), up(s2), up(s3), up(s6)) ---------
__global__ void psp_assemble(const float* __restrict__ x, const float* __restrict__ ppool,
                             float* __restrict__ psp)
{
    long idx = (long)blockIdx.x * 256 + threadIdx.x;
    if (idx >= 18874368L) return;
    int p = (int)(idx % 2304);
    long t = idx / 2304;
    int c = (int)(t % 4096);
    int n = (int)(t / 4096);
    float v;
    if (c < 2048) {
        v = x[((long)n * 2048 + c) * 2304 + p];
    } else {
        int sc = (c - 2048) >> 9;
        int cc = (c - 2048) & 511;
        const int sides[4]  = {1, 2, 3, 6};
        const int outoff[4] = {0, 512, 2560, 7168};
        int s = sides[sc];
        const float* f = ppool + (long)n * 25600 + outoff[sc] + cc * s * s;
        if (s == 1) {
            v = f[0];
        } else {
            int y = p / 48, xx = p % 48;
            float ratio = (float)(s - 1) / 47.0f;
            float sy = y * ratio, sx = xx * ratio;
            int y0 = (int)sy, x0 = (int)sx;
            if (y0 > s - 1) y0 = s - 1;
            if (x0 > s - 1) x0 = s - 1;
            int y1 = min(y0 + 1, s - 1), x1 = min(x0 + 1, s - 1);
            float wy = sy - y0, wx = sx - x0;
            float r0 = f[y0 * s + x0] * (1.f - wx) + f[y0 * s + x1] * wx;
            float r1 = f[y1 * s + x0] * (1.f - wx) + f[y1 * s + x1] * wx;
            v = r0 * (1.f - wy) + r1 * wy;
        }
    }
    psp[idx] = v;
}

// -------- bilinear 48->96 (align_corners), optional ReLU -------------------
template<bool RELU>
__global__ void ups48to96(const float* __restrict__ in, float* __restrict__ out, int total)
{
    int idx = blockIdx.x * 256 + threadIdx.x;
    if (idx >= total) return;
    int p  = idx % 9216;
    int ch = idx / 9216;
    int y = p / 96, x = p % 96;
    const float r = 47.0f / 95.0f;
    float sy = y * r, sx = x * r;
    int y0 = (int)sy, x0 = (int)sx;
    if (y0 > 47) y0 = 47;
    if (x0 > 47) x0 = 47;
    int y1 = min(y0 + 1, 47), x1 = min(x0 + 1, 47);
    float wy = sy - y0, wx = sx - x0;
    const float* f = in + (long)ch * 2304;
    float v0 = f[y0 * 48 + x0] * (1.f - wx) + f[y0 * 48 + x1] * wx;
    float v1 = f[y1 * 48 + x0] * (1.f - wx) + f[y1 * 48 + x1] * wx;
    float v  = v0 * (1.f - wy) + v1 * wy;
    if (RELU) v = fmaxf(v, 0.f);
    out[idx] = v;
}

// -------- attention: energy over 9 dilated taps + softmax ------------------
__global__ void att_kernel(const float* __restrict__ q, const float* __restrict__ kf,
                           float* __restrict__ att)
{
    int p = blockIdx.x * 256 + threadIdx.x;
    int n = blockIdx.y;
    if (p >= 9216) return;
    int y = p / 96, x = p % 96;
    int   offs[9];
    bool  valid[9];
    #pragma unroll
    for (int k = 0; k < 9; k++) {
        int yy = y + (k / 3 - 1) * 2;
        int xx = x + (k % 3 - 1) * 2;
        valid[k] = ((unsigned)yy < 96u) && ((unsigned)xx < 96u);
        offs[k]  = valid[k] ? yy * 96 + xx : 0;
    }
    float e[9];
    #pragma unroll
    for (int k = 0; k < 9; k++) e[k] = 0.f;
    const float* qn = q  + (long)n * 64 * 9216;
    const float* kn = kf + (long)n * 64 * 9216;
    for (int c = 0; c < 64; c++) {
        float qv = qn[c * 9216 + p];
        const float* base = kn + c * 9216;
        #pragma unroll
        for (int k = 0; k < 9; k++) {
            float kv = valid[k] ? base[offs[k]] : 0.f;
            e[k] = fmaf(qv, kv, e[k]);
        }
    }
    float mx = e[0];
    #pragma unroll
    for (int k = 1; k < 9; k++) mx = fmaxf(mx, e[k]);
    float sum = 0.f;
    #pragma unroll
    for (int k = 0; k < 9; k++) { e[k] = __expf(e[k] - mx); sum += e[k]; }
    float inv = 1.f / sum;
    #pragma unroll
    for (int k = 0; k < 9; k++)
        att[(long)n * 82944 + k * 9216 + p] = e[k] * inv;
}

// -------- final: out[o,p] = b[o] + sum_k att[k,p] * z96[o, p+off_k] --------
__global__ void final_kernel(const float* __restrict__ att, const float* __restrict__ z,
                             const float* __restrict__ bias, float* __restrict__ out)
{
    int p = blockIdx.x * 256 + threadIdx.x;
    int o = blockIdx.y;
    int n = blockIdx.z;
    if (p >= 9216) return;
    int y = p / 96, x = p % 96;
    const float* zr = z   + ((long)n * 59 + o) * 9216;
    const float* an = att + (long)n * 82944;
    float acc = bias[o];
    #pragma unroll
    for (int k = 0; k < 9; k++) {
        int yy = y + (k / 3 - 1) * 2;
        int xx = x + (k % 3 - 1) * 2;
        float zv = ((unsigned)yy < 96u && (unsigned)xx < 96u) ? zr[yy * 96 + xx] : 0.f;
        acc = fmaf(an[k * 9216 + p], zv, acc);
    }
    out[((long)n * 59 + o) * 9216 + p] = acc;
}

// ---------------------------------------------------------------------------
extern "C" void kernel_launch(void* const* d_in, const int* in_sizes, int n_in,
                              void* d_out, int out_size)
{
    (void)in_sizes; (void)n_in; (void)out_size;
    const float* c1    = (const float*)d_in[0];
    const float* c2    = (const float*)d_in[1];
    const float* x     = (const float*)d_in[2];
    const float* w_r1  = (const float*)d_in[3];
    const float* bnr1  = (const float*)d_in[4];
    const float* w_r2  = (const float*)d_in[5];
    const float* bnr2  = (const float*)d_in[6];
    const float* w_r3  = (const float*)d_in[7];
    const float* bnr3  = (const float*)d_in[8];
    const float* w_c5  = (const float*)d_in[17];
    const float* bnc5  = (const float*)d_in[18];
    const float* w_c6  = (const float*)d_in[19];
    const float* b_c6  = (const float*)d_in[20];

    float *r1p, *r2p, *t48p, *c2rp, *attp, *poolp, *ppolp, *pspp, *o5p, *z48p, *z96p;
    cudaGetSymbolAddress((void**)&r1p,  g_r1b);
    cudaGetSymbolAddress((void**)&r2p,  g_r2b);
    cudaGetSymbolAddress((void**)&t48p, g_t48);
    cudaGetSymbolAddress((void**)&c2rp, g_c2r);
    cudaGetSymbolAddress((void**)&attp, g_attb);
    cudaGetSymbolAddress((void**)&poolp, g_pool);
    cudaGetSymbolAddress((void**)&ppolp, g_ppol);
    cudaGetSymbolAddress((void**)&pspp, g_psp);
    cudaGetSymbolAddress((void**)&o5p,  g_out5);
    cudaGetSymbolAddress((void**)&z48p, g_z48);
    cudaGetSymbolAddress((void**)&z96p, g_z96);

    // --- query branch: two dilated 3x3 convs (BN+ReLU fused) ---
    gemm_conv<64, 2, true, true, false, false><<<dim3(72, 1, 2), 128>>>(
        w_r1, c1, bnr1, r1p, 64, 2304, 96, 96, 9216, 256L * 9216, 64L * 9216);
    gemm_conv<64, 2, true, true, false, false><<<dim3(72, 1, 2), 128>>>(
        w_r2, r1p, bnr2, r2p, 64, 576, 96, 96, 9216, 64L * 9216, 64L * 9216);

    // --- key branch: 1x1 conv + BN at 48x48, then upsample + ReLU ---
    gemm_conv<64, 0, true, false, false, false><<<dim3(18, 1, 2), 128>>>(
        w_r3, c2, bnr3, t48p, 64, 512, 48, 48, 2304, 512L * 2304, 64L * 2304);
    ups48to96<true><<<4608, 256>>>(t48p, c2rp, 2 * 64 * 9216);

    // --- attention weights ---
    att_kernel<<<dim3(36, 2), 256>>>(r2p, c2rp, attp);

    // --- pyramid pooling ---
    pool_kernel<<<dim3(2048, 2), 64>>>(x, poolp);
    PoolWArgs pa;
    pa.w[0] = (const float*)d_in[9];  pa.bn[0] = (const float*)d_in[10];
    pa.w[1] = (const float*)d_in[11]; pa.bn[1] = (const float*)d_in[12];
    pa.w[2] = (const float*)d_in[13]; pa.bn[2] = (const float*)d_in[14];
    pa.w[3] = (const float*)d_in[15]; pa.bn[3] = (const float*)d_in[16];
    pooled_conv_kernel<<<6400, 256>>>(pa, poolp, ppolp);
    psp_assemble<<<73728, 256>>>(x, ppolp, pspp);

    // --- conv5: 3x3, 4096 -> 512, BN + ReLU (dominant GEMM) ---
    gemm_conv<128, 1, true, true, false, false><<<dim3(18, 4, 2), 256>>>(
        w_c5, pspp, bnc5, o5p, 512, 36864, 48, 48, 2304, 4096L * 2304, 512L * 2304);

    // --- conv6 pulled before upsample/aggregate (1x1, 512 -> 59, no bias) ---
    gemm_conv<64, 0, false, false, true, false><<<dim3(18, 1, 2), 128>>>(
        w_c6, o5p, nullptr, z48p, 59, 512, 48, 48, 2304, 512L * 2304, 59L * 2304);
    ups48to96<false><<<4248, 256>>>(z48p, z96p, 2 * 59 * 9216);

    // --- attention aggregation + bias -> final output ---
    final_kernel<<<dim3(36, 59, 2), 256>>>(attp, z96p, b_c6, (float*)d_out);
}

// round 6
// speedup vs baseline: 1.6627x; 1.6627x over previous
#include <cuda_runtime.h>
#include <cstdint>

// ---------------- scratch (device globals; no allocation allowed) ----------
__device__ float g_r1b [1179648];  // [2][64][96][96]  after refine conv1
__device__ float g_r2b [1179648];  // [2][64][96][96]  query features q
__device__ float g_t48 [294912];   // [2][64][48][48]  bn(conv1x1(c2))
__device__ float g_c2r [1179648];  // [2][64][96][96]  relu(upsample(t48)) = keys
__device__ float g_attb[165888];   // [2][9][9216]     softmax attention
__device__ float g_pool[204800];   // [2][2048*50]     pooled x
__device__ float g_ppol[51200];    // [2][512*50]      relu(bn(1x1 conv)) of pooled
__device__ float g_psp [18874368]; // [2][4096][48][48] concat psp features
__device__ float g_out5[2359296];  // [2][512][48][48] conv5 output
__device__ float g_z48 [271872];   // [2][59][48][48]  conv6(out) (no bias)
__device__ float g_z96 [1087488];  // [2][59][96][96]  upsampled z

// ===========================================================================
// mma.sync tf32 helper (baseline PTX ISA — works on compute_103)
// ===========================================================================
__device__ __forceinline__ void mma16n8k8(float* c, const uint32_t* a, const uint32_t* b)
{
    asm volatile(
        "mma.sync.aligned.m16n8k8.row.col.f32.tf32.tf32.f32 "
        "{%0,%1,%2,%3}, {%4,%5,%6,%7}, {%8,%9}, {%0,%1,%2,%3};"
        : "+f"(c[0]), "+f"(c[1]), "+f"(c[2]), "+f"(c[3])
        : "r"(a[0]), "r"(a[1]), "r"(a[2]), "r"(a[3]), "r"(b[0]), "r"(b[1]));
}

// ===========================================================================
// conv5 via tf32 mma.sync, implicit im2col.
//   Out[m,p] = BNReLU( sum_k W[m,k] * B[p,k] ),  k = cin*9 + tap (3x3, pad 1)
//   M=512, N=2304 px, K=36864. CTA tile 128x128, KC=32, 8 warps (warp 32x64).
//   SMEM: As/Bs stored [k][m]/[k][n], stride 136 floats (conflict-free frags).
// ===========================================================================
#define SA 136
#define KC 32
#define NCH 1152   // 36864 / 32

__global__ void __launch_bounds__(256, 1)
c5_mma_kernel(const float* __restrict__ Aw, const float* __restrict__ psp,
              const float* __restrict__ bnp, float* __restrict__ Out)
{
    extern __shared__ float sm[];
    // layout: As0 | Bs0 | As1 | Bs1, each KC*SA floats
    float* As[2] = { sm,            sm + 2 * KC * SA };
    float* Bs[2] = { sm + KC * SA,  sm + 3 * KC * SA };

    const int t    = threadIdx.x;
    const int wid  = t >> 5;
    const int lane = t & 31;
    const int gid  = lane >> 2;   // groupID (row within fragment)
    const int tig  = lane & 3;    // thread-in-group (col within fragment)
    const int wm   = (wid & 3) * 32;
    const int wn   = (wid >> 2) * 64;

    const int img = blockIdx.z;
    const int bm  = blockIdx.y * 128;
    const int bp0 = blockIdx.x * 128;
    const float* Bn = psp + (long)img * 4096 * 2304;

    // A loader geometry: thread covers one m-row half of k-chunk
    const int a_m = t >> 1;             // 0..127
    const int a_k = (t & 1) * 16;       // 0 / 16
    const float* Abase = Aw + (long)(bm + a_m) * 36864 + a_k;

    // B loader geometry: thread covers 16 consecutive pixels at one k-row
    const int b_k  = t >> 3;            // 0..31
    const int b_n0 = (t & 7) * 16;
    const int pg0  = bp0 + b_n0;
    const int py0  = pg0 / 48;
    const int px0  = pg0 - py0 * 48;    // 0/16/32 -> px0+15 <= 47, no row wrap

    float4 arv[4];
    float  brv[16];

    auto fetch = [&](int k0) {
        const float* ap = Abase + k0;
        #pragma unroll
        for (int i = 0; i < 4; i++)
            arv[i] = *reinterpret_cast<const float4*>(ap + i * 4);
        int k   = k0 + b_k;
        int cin = k / 9;
        int tap = k - cin * 9;
        int dy  = tap / 3;
        int dx  = tap - dy * 3;
        int y   = py0 + dy - 1;
        bool vy = (unsigned)y < 48u;
        int  xb = px0 + dx - 1;
        const float* bp = Bn + (long)cin * 2304 + y * 48 + xb;
        #pragma unroll
        for (int j = 0; j < 16; j++) {
            int x = xb + j;
            brv[j] = (vy && (unsigned)x < 48u) ? __ldg(bp + j) : 0.f;
        }
    };
    auto sts = [&](int buf) {
        float* A = As[buf];
        float* B = Bs[buf];
        #pragma unroll
        for (int i = 0; i < 4; i++) {
            A[(a_k + i * 4 + 0) * SA + a_m] = arv[i].x;
            A[(a_k + i * 4 + 1) * SA + a_m] = arv[i].y;
            A[(a_k + i * 4 + 2) * SA + a_m] = arv[i].z;
            A[(a_k + i * 4 + 3) * SA + a_m] = arv[i].w;
        }
        #pragma unroll
        for (int j4 = 0; j4 < 4; j4++)
            *reinterpret_cast<float4*>(B + b_k * SA + b_n0 + j4 * 4) =
                make_float4(brv[j4 * 4], brv[j4 * 4 + 1], brv[j4 * 4 + 2], brv[j4 * 4 + 3]);
    };

    float acc[2][8][4];
    #pragma unroll
    for (int mt = 0; mt < 2; mt++)
        #pragma unroll
        for (int nt = 0; nt < 8; nt++)
            #pragma unroll
            for (int i = 0; i < 4; i++) acc[mt][nt][i] = 0.f;

    fetch(0);
    sts(0);
    __syncthreads();

    for (int it = 0; it < NCH; it++) {
        const int buf = it & 1;
        if (it + 1 < NCH) fetch((it + 1) * KC);
        const float* A = As[buf];
        const float* B = Bs[buf];
        #pragma unroll
        for (int s = 0; s < 4; s++) {
            uint32_t af[2][4];
            uint32_t bf[8][2];
            #pragma unroll
            for (int mt = 0; mt < 2; mt++) {
                const float* ap = A + (s * 8 + tig) * SA + wm + mt * 16 + gid;
                af[mt][0] = __float_as_uint(ap[0]);
                af[mt][1] = __float_as_uint(ap[8]);
                af[mt][2] = __float_as_uint(ap[4 * SA]);
                af[mt][3] = __float_as_uint(ap[4 * SA + 8]);
            }
            #pragma unroll
            for (int nt = 0; nt < 8; nt++) {
                const float* bp = B + (s * 8 + tig) * SA + wn + nt * 8 + gid;
                bf[nt][0] = __float_as_uint(bp[0]);
                bf[nt][1] = __float_as_uint(bp[4 * SA]);
            }
            #pragma unroll
            for (int mt = 0; mt < 2; mt++)
                #pragma unroll
                for (int nt = 0; nt < 8; nt++)
                    mma16n8k8(acc[mt][nt], af[mt], bf[nt]);
        }
        if (it + 1 < NCH) sts(buf ^ 1);
        __syncthreads();
    }

    // epilogue: BN + ReLU, write float2 per (mt, nt, half)
    #pragma unroll
    for (int mt = 0; mt < 2; mt++) {
        const int m0 = bm + wm + mt * 16 + gid;
        #pragma unroll
        for (int half = 0; half < 2; half++) {
            const int m = m0 + half * 8;
            const float g  = bnp[m], be = bnp[512 + m];
            const float mu = bnp[1024 + m], va = bnp[1536 + m];
            const float scale = g * rsqrtf(va + 1e-5f);
            const float shift = be - mu * scale;
            float* On = Out + ((long)img * 512 + m) * 2304 + bp0 + wn + tig * 2;
            #pragma unroll
            for (int nt = 0; nt < 8; nt++) {
                float2 v;
                v.x = fmaxf(fmaf(acc[mt][nt][half * 2],     scale, shift), 0.f);
                v.y = fmaxf(fmaf(acc[mt][nt][half * 2 + 1], scale, shift), 0.f);
                *reinterpret_cast<float2*>(On + nt * 8) = v;
            }
        }
    }
}

// ================= fp32 SGEMM (small convs) ================================
template<int TM, int DIL, bool BN, bool RELU, bool MCHECK, bool NCHECK>
__global__ void __launch_bounds__((TM/8)*16, 1)
gemm_conv(const float* __restrict__ A, const float* __restrict__ Bin,
          const float* __restrict__ bnp, float* __restrict__ Out,
          int M, int K, int H, int W, int Npix,
          long inStride, long outStride)
{
    constexpr int TN   = 128;
    constexpr int NT   = (TM / 8) * (TN / 8);
    constexpr int BVEC = (NT == 256) ? 4 : 8;

    __shared__ float As_[2][8][TM];
    __shared__ float Bs_[2][8][TN];

    const int tid = threadIdx.x;
    const int img = blockIdx.z;
    const float* Bn = Bin + (long)img * inStride;
    float*       On = Out + (long)img * outStride;
    const int bm  = blockIdx.y * TM;
    const int bp0 = blockIdx.x * TN;
    const int tr  = tid / 16;
    const int tc  = tid % 16;

    const int am = tid >> 1;
    const int ak = (tid & 1) * 4;
    const int bk = tid / (TN / BVEC);
    const int bp = (tid % (TN / BVEC)) * BVEC;

    float4 aReg;
    float  bReg[BVEC];

    auto fetch = [&](int k0) {
        int m = bm + am;
        if (!MCHECK || m < M)
            aReg = *reinterpret_cast<const float4*>(A + (long)m * K + k0 + ak);
        else
            aReg = make_float4(0.f, 0.f, 0.f, 0.f);
        int k = k0 + bk;
        if (DIL == 0) {
            const float* row = Bn + (long)k * Npix;
            if (!NCHECK) {
                #pragma unroll
                for (int j = 0; j < BVEC; j += 4) {
                    float4 v = *reinterpret_cast<const float4*>(row + bp0 + bp + j);
                    bReg[j] = v.x; bReg[j+1] = v.y; bReg[j+2] = v.z; bReg[j+3] = v.w;
                }
            } else {
                #pragma unroll
                for (int j = 0; j < BVEC; j++) {
                    int p = bp0 + bp + j;
                    bReg[j] = (p < Npix) ? row[p] : 0.f;
                }
            }
        } else {
            int cin = k / 9;
            int tap = k - cin * 9;
            int oy  = (tap / 3 - 1) * DIL;
            int ox  = (tap % 3 - 1) * DIL;
            const float* src = Bn + (long)cin * (H * W);
            #pragma unroll
            for (int j = 0; j < BVEC; j++) {
                int p  = bp0 + bp + j;
                int py = p / W;
                int px = p - py * W;
                int y  = py + oy;
                int x  = px + ox;
                bReg[j] = ((unsigned)y < (unsigned)H && (unsigned)x < (unsigned)W)
                          ? src[y * W + x] : 0.f;
            }
        }
    };
    auto put = [&](int buf) {
        As_[buf][ak + 0][am] = aReg.x;
        As_[buf][ak + 1][am] = aReg.y;
        As_[buf][ak + 2][am] = aReg.z;
        As_[buf][ak + 3][am] = aReg.w;
        #pragma unroll
        for (int j = 0; j < BVEC; j++) Bs_[buf][bk][bp + j] = bReg[j];
    };

    float acc[8][8];
    #pragma unroll
    for (int i = 0; i < 8; i++)
        #pragma unroll
        for (int j = 0; j < 8; j++) acc[i][j] = 0.f;

    fetch(0);
    put(0);
    __syncthreads();

    const int nK = K / 8;
    int buf = 0;
    for (int it = 0; it < nK; it++) {
        if (it + 1 < nK) fetch((it + 1) * 8);
        #pragma unroll
        for (int kk = 0; kk < 8; kk++) {
            float4 a0 = *reinterpret_cast<const float4*>(&As_[buf][kk][tr * 8]);
            float4 a1 = *reinterpret_cast<const float4*>(&As_[buf][kk][tr * 8 + 4]);
            float4 b0 = *reinterpret_cast<const float4*>(&Bs_[buf][kk][tc * 8]);
            float4 b1 = *reinterpret_cast<const float4*>(&Bs_[buf][kk][tc * 8 + 4]);
            float av[8] = {a0.x, a0.y, a0.z, a0.w, a1.x, a1.y, a1.z, a1.w};
            float bv[8] = {b0.x, b0.y, b0.z, b0.w, b1.x, b1.y, b1.z, b1.w};
            #pragma unroll
            for (int i = 0; i < 8; i++)
                #pragma unroll
                for (int j = 0; j < 8; j++)
                    acc[i][j] = fmaf(av[i], bv[j], acc[i][j]);
        }
        if (it + 1 < nK) put(buf ^ 1);
        __syncthreads();
        buf ^= 1;
    }

    #pragma unroll
    for (int i = 0; i < 8; i++) {
        int m = bm + tr * 8 + i;
        if (MCHECK && m >= M) continue;
        float scale = 1.f, shift = 0.f;
        if (BN) {
            float g  = bnp[m];
            float be = bnp[M + m];
            float mu = bnp[2 * M + m];
            float va = bnp[3 * M + m];
            scale = g * rsqrtf(va + 1e-5f);
            shift = be - mu * scale;
        }
        #pragma unroll
        for (int j = 0; j < 8; j++) {
            int p = bp0 + tc * 8 + j;
            if (NCHECK && p >= Npix) continue;
            float v = acc[i][j];
            if (BN)   v = fmaf(v, scale, shift);
            if (RELU) v = fmaxf(v, 0.f);
            On[(long)m * Npix + p] = v;
        }
    }
}

// -------- adaptive avg pool of x at scales 1,2,3,6 -------------------------
__global__ void pool_kernel(const float* __restrict__ x, float* __restrict__ pool)
{
    __shared__ float sm[2304];
    const int cin = blockIdx.x;
    const int n   = blockIdx.y;
    const float* src = x + ((long)n * 2048 + cin) * 2304;
    for (int i = threadIdx.x; i < 2304; i += blockDim.x) sm[i] = src[i];
    __syncthreads();
    int r = threadIdx.x;
    if (r < 50) {
        int sc, pi;
        if      (r < 1)  { sc = 0; pi = r; }
        else if (r < 5)  { sc = 1; pi = r - 1; }
        else if (r < 14) { sc = 2; pi = r - 5; }
        else             { sc = 3; pi = r - 14; }
        const int sides[4] = {1, 2, 3, 6};
        const int inoff[4] = {0, 2048, 10240, 28672};
        int side = sides[sc];
        int iy = pi / side, ix = pi % side;
        int bs = 48 / side;
        float s = 0.f;
        for (int yy = iy * bs; yy < (iy + 1) * bs; yy++)
            for (int xx = ix * bs; xx < (ix + 1) * bs; xx++)
                s += sm[yy * 48 + xx];
        pool[(long)n * 102400 + inoff[sc] + cin * (side * side) + pi] = s / (float)(bs * bs);
    }
}

struct PoolWArgs { const float* w[4]; const float* bn[4]; };

__global__ void pooled_conv_kernel(PoolWArgs args, const float* __restrict__ pool,
                                   float* __restrict__ ppool)
{
    int gw   = (blockIdx.x * blockDim.x + threadIdx.x) >> 5;
    int lane = threadIdx.x & 31;
    if (gw >= 51200) return;
    int n  = gw / 25600;
    int t  = gw % 25600;
    int pg = t / 512;
    int co = t % 512;
    int sc, pi;
    if      (pg < 1)  { sc = 0; pi = pg; }
    else if (pg < 5)  { sc = 1; pi = pg - 1; }
    else if (pg < 14) { sc = 2; pi = pg - 5; }
    else              { sc = 3; pi = pg - 14; }
    const int ssq[4]    = {1, 4, 9, 36};
    const int inoff[4]  = {0, 2048, 10240, 28672};
    const int outoff[4] = {0, 512, 2560, 7168};
    const float* w  = args.w[sc] + (long)co * 2048;
    const float* pb = pool + (long)n * 102400 + inoff[sc] + pi;
    int stride = ssq[sc];
    float acc = 0.f;
    for (int c = lane; c < 2048; c += 32)
        acc = fmaf(w[c], pb[(long)c * stride], acc);
    #pragma unroll
    for (int s = 16; s; s >>= 1) acc += __shfl_xor_sync(0xffffffffu, acc, s);
    if (lane == 0) {
        const float* bnp = args.bn[sc];
        float scale = bnp[co] * rsqrtf(bnp[1536 + co] + 1e-5f);
        float v = fmaf(acc, scale, bnp[512 + co] - bnp[1024 + co] * scale);
        ppool[(long)n * 25600 + outoff[sc] + co * stride + pi] = fmaxf(v, 0.f);
    }
}

__global__ void psp_assemble(const float* __restrict__ x, const float* __restrict__ ppool,
                             float* __restrict__ psp)
{
    long idx = (long)blockIdx.x * 256 + threadIdx.x;
    if (idx >= 18874368L) return;
    int p = (int)(idx % 2304);
    long t = idx / 2304;
    int c = (int)(t % 4096);
    int n = (int)(t / 4096);
    float v;
    if (c < 2048) {
        v = x[((long)n * 2048 + c) * 2304 + p];
    } else {
        int sc = (c - 2048) >> 9;
        int cc = (c - 2048) & 511;
        const int sides[4]  = {1, 2, 3, 6};
        const int outoff[4] = {0, 512, 2560, 7168};
        int s = sides[sc];
        const float* f = ppool + (long)n * 25600 + outoff[sc] + cc * s * s;
        if (s == 1) {
            v = f[0];
        } else {
            int y = p / 48, xx = p % 48;
            float ratio = (float)(s - 1) / 47.0f;
            float sy = y * ratio, sx = xx * ratio;
            int y0 = (int)sy, x0 = (int)sx;
            if (y0 > s - 1) y0 = s - 1;
            if (x0 > s - 1) x0 = s - 1;
            int y1 = min(y0 + 1, s - 1), x1 = min(x0 + 1, s - 1);
            float wy = sy - y0, wx = sx - x0;
            float r0 = f[y0 * s + x0] * (1.f - wx) + f[y0 * s + x1] * wx;
            float r1 = f[y1 * s + x0] * (1.f - wx) + f[y1 * s + x1] * wx;
            v = r0 * (1.f - wy) + r1 * wy;
        }
    }
    psp[idx] = v;
}

template<bool RELU>
__global__ void ups48to96(const float* __restrict__ in, float* __restrict__ out, int total)
{
    int idx = blockIdx.x * 256 + threadIdx.x;
    if (idx >= total) return;
    int p  = idx % 9216;
    int ch = idx / 9216;
    int y = p / 96, x = p % 96;
    const float r = 47.0f / 95.0f;
    float sy = y * r, sx = x * r;
    int y0 = (int)sy, x0 = (int)sx;
    if (y0 > 47) y0 = 47;
    if (x0 > 47) x0 = 47;
    int y1 = min(y0 + 1, 47), x1 = min(x0 + 1, 47);
    float wy = sy - y0, wx = sx - x0;
    const float* f = in + (long)ch * 2304;
    float v0 = f[y0 * 48 + x0] * (1.f - wx) + f[y0 * 48 + x1] * wx;
    float v1 = f[y1 * 48 + x0] * (1.f - wx) + f[y1 * 48 + x1] * wx;
    float v  = v0 * (1.f - wy) + v1 * wy;
    if (RELU) v = fmaxf(v, 0.f);
    out[idx] = v;
}

__global__ void att_kernel(const float* __restrict__ q, const float* __restrict__ kf,
                           float* __restrict__ att)
{
    int p = blockIdx.x * 256 + threadIdx.x;
    int n = blockIdx.y;
    if (p >= 9216) return;
    int y = p / 96, x = p % 96;
    int   offs[9];
    bool  valid[9];
    #pragma unroll
    for (int k = 0; k < 9; k++) {
        int yy = y + (k / 3 - 1) * 2;
        int xx = x + (k % 3 - 1) * 2;
        valid[k] = ((unsigned)yy < 96u) && ((unsigned)xx < 96u);
        offs[k]  = valid[k] ? yy * 96 + xx : 0;
    }
    float e[9];
    #pragma unroll
    for (int k = 0; k < 9; k++) e[k] = 0.f;
    const float* qn = q  + (long)n * 64 * 9216;
    const float* kn = kf + (long)n * 64 * 9216;
    for (int c = 0; c < 64; c++) {
        float qv = qn[c * 9216 + p];
        const float* base = kn + c * 9216;
        #pragma unroll
        for (int k = 0; k < 9; k++) {
            float kv = valid[k] ? base[offs[k]] : 0.f;
            e[k] = fmaf(qv, kv, e[k]);
        }
    }
    float mx = e[0];
    #pragma unroll
    for (int k = 1; k < 9; k++) mx = fmaxf(mx, e[k]);
    float sum = 0.f;
    #pragma unroll
    for (int k = 0; k < 9; k++) { e[k] = __expf(e[k] - mx); sum += e[k]; }
    float inv = 1.f / sum;
    #pragma unroll
    for (int k = 0; k < 9; k++)
        att[(long)n * 82944 + k * 9216 + p] = e[k] * inv;
}

__global__ void final_kernel(const float* __restrict__ att, const float* __restrict__ z,
                             const float* __restrict__ bias, float* __restrict__ out)
{
    int p = blockIdx.x * 256 + threadIdx.x;
    int o = blockIdx.y;
    int n = blockIdx.z;
    if (p >= 9216) return;
    int y = p / 96, x = p % 96;
    const float* zr = z   + ((long)n * 59 + o) * 9216;
    const float* an = att + (long)n * 82944;
    float acc = bias[o];
    #pragma unroll
    for (int k = 0; k < 9; k++) {
        int yy = y + (k / 3 - 1) * 2;
        int xx = x + (k % 3 - 1) * 2;
        float zv = ((unsigned)yy < 96u && (unsigned)xx < 96u) ? zr[yy * 96 + xx] : 0.f;
        acc = fmaf(an[k * 9216 + p], zv, acc);
    }
    out[((long)n * 59 + o) * 9216 + p] = acc;
}

// ---------------------------------------------------------------------------
extern "C" void kernel_launch(void* const* d_in, const int* in_sizes, int n_in,
                              void* d_out, int out_size)
{
    (void)in_sizes; (void)n_in; (void)out_size;
    const float* c1    = (const float*)d_in[0];
    const float* c2    = (const float*)d_in[1];
    const float* x     = (const float*)d_in[2];
    const float* w_r1  = (const float*)d_in[3];
    const float* bnr1  = (const float*)d_in[4];
    const float* w_r2  = (const float*)d_in[5];
    const float* bnr2  = (const float*)d_in[6];
    const float* w_r3  = (const float*)d_in[7];
    const float* bnr3  = (const float*)d_in[8];
    const float* w_c5  = (const float*)d_in[17];
    const float* bnc5  = (const float*)d_in[18];
    const float* w_c6  = (const float*)d_in[19];
    const float* b_c6  = (const float*)d_in[20];

    float *r1p, *r2p, *t48p, *c2rp, *attp, *poolp, *ppolp, *pspp, *o5p, *z48p, *z96p;
    cudaGetSymbolAddress((void**)&r1p,  g_r1b);
    cudaGetSymbolAddress((void**)&r2p,  g_r2b);
    cudaGetSymbolAddress((void**)&t48p, g_t48);
    cudaGetSymbolAddress((void**)&c2rp, g_c2r);
    cudaGetSymbolAddress((void**)&attp, g_attb);
    cudaGetSymbolAddress((void**)&poolp, g_pool);
    cudaGetSymbolAddress((void**)&ppolp, g_ppol);
    cudaGetSymbolAddress((void**)&pspp, g_psp);
    cudaGetSymbolAddress((void**)&o5p,  g_out5);
    cudaGetSymbolAddress((void**)&z48p, g_z48);
    cudaGetSymbolAddress((void**)&z96p, g_z96);

    const int c5_smem = 4 * KC * SA * sizeof(float);  // 69632 B
    cudaFuncSetAttribute(c5_mma_kernel, cudaFuncAttributeMaxDynamicSharedMemorySize, c5_smem);

    // --- query branch ---
    gemm_conv<64, 2, true, true, false, false><<<dim3(72, 1, 2), 128>>>(
        w_r1, c1, bnr1, r1p, 64, 2304, 96, 96, 9216, 256L * 9216, 64L * 9216);
    gemm_conv<64, 2, true, true, false, false><<<dim3(72, 1, 2), 128>>>(
        w_r2, r1p, bnr2, r2p, 64, 576, 96, 96, 9216, 64L * 9216, 64L * 9216);

    // --- key branch ---
    gemm_conv<64, 0, true, false, false, false><<<dim3(18, 1, 2), 128>>>(
        w_r3, c2, bnr3, t48p, 64, 512, 48, 48, 2304, 512L * 2304, 64L * 2304);
    ups48to96<true><<<4608, 256>>>(t48p, c2rp, 2 * 64 * 9216);

    // --- attention weights ---
    att_kernel<<<dim3(36, 2), 256>>>(r2p, c2rp, attp);

    // --- pyramid pooling ---
    pool_kernel<<<dim3(2048, 2), 64>>>(x, poolp);
    PoolWArgs pa;
    pa.w[0] = (const float*)d_in[9];  pa.bn[0] = (const float*)d_in[10];
    pa.w[1] = (const float*)d_in[11]; pa.bn[1] = (const float*)d_in[12];
    pa.w[2] = (const float*)d_in[13]; pa.bn[2] = (const float*)d_in[14];
    pa.w[3] = (const float*)d_in[15]; pa.bn[3] = (const float*)d_in[16];
    pooled_conv_kernel<<<6400, 256>>>(pa, poolp, ppolp);
    psp_assemble<<<73728, 256>>>(x, ppolp, pspp);

    // --- conv5 on tensor cores (mma.sync tf32) ---
    c5_mma_kernel<<<dim3(18, 4, 2), 256, c5_smem>>>(w_c5, pspp, bnc5, o5p);

    // --- conv6 pulled before upsample/aggregate ---
    gemm_conv<64, 0, false, false, true, false><<<dim3(18, 1, 2), 128>>>(
        w_c6, o5p, nullptr, z48p, 59, 512, 48, 48, 2304, 512L * 2304, 59L * 2304);
    ups48to96<false><<<4248, 256>>>(z48p, z96p, 2 * 59 * 9216);

    // --- attention aggregation + bias ---
    final_kernel<<<dim3(36, 59, 2), 256>>>(attp, z96p, b_c6, (float*)d_out);
}